// round 2
// baseline (speedup 1.0000x reference)
#include <cuda_runtime.h>
#include <stdint.h>

// Problem shape (fixed by the dataset): 100000 users + 50000 items, D=64, E=2M.
#define MAXN 150016            // padded node count
#define MAXE 2000000
#define D 64
#define D2 32                  // D in float2

// -------- static device scratch (no allocations allowed) --------
__device__ int   g_deg[MAXN];
__device__ float g_dis[MAXN];
__device__ int   g_off[MAXN + 1];
__device__ int   g_cur[MAXN];
__device__ int   g_csr[MAXE];
__device__ float g_t0[(size_t)MAXN * D];
__device__ float g_t1[(size_t)MAXN * D];

// -------- kernels --------

__global__ void zero_deg_kernel(int N) {
    int i = blockIdx.x * blockDim.x + threadIdx.x;
    if (i < N) g_deg[i] = 0;
}

__global__ void count_deg_kernel(const int* __restrict__ dst, int E, int N) {
    int e = blockIdx.x * blockDim.x + threadIdx.x;
    if (e < E) {
        int d = dst[e];
        if ((unsigned)d < (unsigned)N) atomicAdd(&g_deg[d], 1);
    }
}

__global__ void dis_kernel(int N) {
    int i = blockIdx.x * blockDim.x + threadIdx.x;
    if (i < N) {
        int d = g_deg[i];
        g_dis[i] = (d > 0) ? rsqrtf((float)d) : 0.0f;
    }
}

// Single-block exclusive scan over g_deg -> g_off (size N+1), also seeds g_cur.
__global__ void scan_kernel(int N) {
    __shared__ int sh[1024];
    __shared__ int carry;
    int t = threadIdx.x;
    if (t == 0) { carry = 0; g_off[0] = 0; }
    __syncthreads();
    for (int base = 0; base < N; base += 1024) {
        int i = base + t;
        int v = (i < N) ? g_deg[i] : 0;
        sh[t] = v;
        __syncthreads();
        // Hillis-Steele inclusive scan
        #pragma unroll
        for (int off = 1; off < 1024; off <<= 1) {
            int add = (t >= off) ? sh[t - off] : 0;
            __syncthreads();
            sh[t] += add;
            __syncthreads();
        }
        int incl = sh[t];
        int c = carry;
        if (i < N) {
            g_off[i + 1] = c + incl;     // inclusive -> offsets shifted by 1
            g_cur[i]     = c + incl - v; // exclusive (start cursor)
        }
        __syncthreads();
        if (t == 1023) carry = c + sh[1023];
        __syncthreads();
    }
}

__global__ void scatter_kernel(const int* __restrict__ src,
                               const int* __restrict__ dst, int E, int N) {
    int e = blockIdx.x * blockDim.x + threadIdx.x;
    if (e < E) {
        int d = dst[e];
        int s = src[e];
        if ((unsigned)d < (unsigned)N && (unsigned)s < (unsigned)N) {
            int pos = atomicAdd(&g_cur[d], 1);
            if ((unsigned)pos < (unsigned)MAXE) g_csr[pos] = s;
        }
    }
}

// Initialize acc (=d_out) with emb0 and g_t0 with dis[u]*emb0[u].
__global__ void init_kernel(const float* __restrict__ emb_users,
                            const float* __restrict__ emb_items,
                            float* __restrict__ acc,
                            int nu_elems, int total_elems) {
    int idx = blockIdx.x * blockDim.x + threadIdx.x;
    if (idx < total_elems) {
        float v = (idx < nu_elems) ? emb_users[idx] : emb_items[idx - nu_elems];
        acc[idx] = v;
        g_t0[idx] = g_dis[idx >> 6] * v;
    }
}

// One propagation layer. Warp per node; each lane owns one float2 (2 cols).
// inbuf selects g_t0/g_t1 as input (output goes to the other).
// last!=0: fold final 1/25 scale into acc and skip writing t_out.
__global__ void __launch_bounds__(256)
layer_kernel(float* __restrict__ acc, int N, int inbuf, int last) {
    int gtid = blockIdx.x * blockDim.x + threadIdx.x;
    int node = gtid >> 5;
    int lane = gtid & 31;
    if (node >= N) return;

    const float2* __restrict__ tin =
        (const float2*)(inbuf ? g_t1 : g_t0);
    float2* __restrict__ tout =
        (float2*)(inbuf ? g_t0 : g_t1);

    int s = g_off[node];
    int e = g_off[node + 1];

    float ax = 0.0f, ay = 0.0f;
    int p = s;
    // 2-deep software pipeline for MLP
    for (; p + 1 < e; p += 2) {
        int u0 = g_csr[p];
        int u1 = g_csr[p + 1];
        float2 v0 = __ldg(&tin[(size_t)u0 * D2 + lane]);
        float2 v1 = __ldg(&tin[(size_t)u1 * D2 + lane]);
        ax += v0.x; ay += v0.y;
        ax += v1.x; ay += v1.y;
    }
    if (p < e) {
        int u0 = g_csr[p];
        float2 v0 = __ldg(&tin[(size_t)u0 * D2 + lane]);
        ax += v0.x; ay += v0.y;
    }

    float dv = g_dis[node];
    float ex = dv * ax;           // emb_new for this node/cols
    float ey = dv * ay;

    size_t oidx = (size_t)node * D2 + lane;
    float2* acc2 = (float2*)acc;
    float2 a = acc2[oidx];
    if (last) {
        const float sc = 1.0f / 25.0f;
        a.x = (a.x + ex) * sc;
        a.y = (a.y + ey) * sc;
        acc2[oidx] = a;
    } else {
        a.x += ex;
        a.y += ey;
        acc2[oidx] = a;
        float2 tv;
        tv.x = dv * ex;           // t_next = dis[v] * emb_new
        tv.y = dv * ey;
        tout[oidx] = tv;
    }
}

// -------- launch --------
extern "C" void kernel_launch(void* const* d_in, const int* in_sizes, int n_in,
                              void* d_out, int out_size) {
    const float* emb_users = (const float*)d_in[0];
    const float* emb_items = (const float*)d_in[1];
    const int*   edge      = (const int*)d_in[2];   // int32 (JAX x64 disabled)

    int nu_elems = in_sizes[0];          // num_users * 64
    int ni_elems = in_sizes[1];          // num_items * 64
    int E        = in_sizes[2] / 2;
    int NU = nu_elems / D;
    int NI = ni_elems / D;
    int N  = NU + NI;

    const int* src = edge;
    const int* dst = edge + E;
    float* acc = (float*)d_out;

    const int T = 256;

    zero_deg_kernel<<<(N + T - 1) / T, T>>>(N);
    count_deg_kernel<<<(E + T - 1) / T, T>>>(dst, E, N);
    dis_kernel<<<(N + T - 1) / T, T>>>(N);
    scan_kernel<<<1, 1024>>>(N);
    scatter_kernel<<<(E + T - 1) / T, T>>>(src, dst, E, N);

    int total = N * D;
    init_kernel<<<(total + T - 1) / T, T>>>(emb_users, emb_items, acc, nu_elems, total);

    int layer_blocks = (N * 32 + T - 1) / T;   // warp per node
    layer_kernel<<<layer_blocks, T>>>(acc, N, /*inbuf=*/0, /*last=*/0); // t0 -> t1
    layer_kernel<<<layer_blocks, T>>>(acc, N, /*inbuf=*/1, /*last=*/0); // t1 -> t0
    layer_kernel<<<layer_blocks, T>>>(acc, N, /*inbuf=*/0, /*last=*/0); // t0 -> t1
    layer_kernel<<<layer_blocks, T>>>(acc, N, /*inbuf=*/1, /*last=*/1); // t1, final scale
}

// round 3
// speedup vs baseline: 1.5198x; 1.5198x over previous
#include <cuda_runtime.h>
#include <stdint.h>

// Problem shape (fixed by the dataset): 100000 users + 50000 items, D=64, E=2M.
#define MAXN 150016            // padded node count
#define MAXE 2000000
#define D 64
#define D2 32                  // D in float2
#define SCAN_T 1024
#define MAX_BLOCKS 256         // ceil(MAXN/1024) = 147

// -------- static device scratch (no allocations allowed) --------
__device__ int   g_deg[MAXN];
__device__ float g_dis[MAXN];
__device__ int   g_off[MAXN + 1];
__device__ int   g_cur[MAXN];
__device__ int   g_csr[MAXE];
__device__ int   g_scan[MAXN];        // inclusive per-block scan
__device__ int   g_bsum[MAX_BLOCKS];  // per-block totals
__device__ int   g_boff[MAX_BLOCKS];  // exclusive scan of block totals
__device__ float g_t0[(size_t)MAXN * D];
__device__ float g_t1[(size_t)MAXN * D];

// -------- kernels --------

__global__ void zero_deg_kernel(int N) {
    int i = blockIdx.x * blockDim.x + threadIdx.x;
    if (i < N) g_deg[i] = 0;
}

__global__ void count_deg_kernel(const int* __restrict__ dst, int E, int N) {
    int e = blockIdx.x * blockDim.x + threadIdx.x;
    if (e < E) {
        int d = dst[e];
        if ((unsigned)d < (unsigned)N) atomicAdd(&g_deg[d], 1);
    }
}

// Phase 1: per-block inclusive scan of g_deg (1024 elems/block) via warp shuffles.
__global__ void __launch_bounds__(SCAN_T)
scan1_kernel(int N) {
    __shared__ int wsum[32];
    int t = threadIdx.x;
    int i = blockIdx.x * SCAN_T + t;
    int v = (i < N) ? g_deg[i] : 0;

    // warp inclusive scan
    int x = v;
    #pragma unroll
    for (int off = 1; off < 32; off <<= 1) {
        int y = __shfl_up_sync(0xffffffff, x, off);
        if ((t & 31) >= off) x += y;
    }
    if ((t & 31) == 31) wsum[t >> 5] = x;
    __syncthreads();

    // scan the 32 warp sums in warp 0
    if (t < 32) {
        int w = wsum[t];
        #pragma unroll
        for (int off = 1; off < 32; off <<= 1) {
            int y = __shfl_up_sync(0xffffffff, w, off);
            if (t >= off) w += y;
        }
        wsum[t] = w;
    }
    __syncthreads();

    int base = (t >= 32) ? wsum[(t >> 5) - 1] : 0;
    int incl = base + x;
    if (i < N) g_scan[i] = incl;
    if (t == SCAN_T - 1) g_bsum[blockIdx.x] = incl;
}

// Phase 2: single warp scans block sums (exclusive) -> g_boff.
__global__ void scan2_kernel(int nblocks) {
    __shared__ int carry_s;
    int t = threadIdx.x;
    if (t == 0) carry_s = 0;
    __syncthreads();
    for (int base = 0; base < nblocks; base += 32) {
        int i = base + t;
        int v = (i < nblocks) ? g_bsum[i] : 0;
        int x = v;
        #pragma unroll
        for (int off = 1; off < 32; off <<= 1) {
            int y = __shfl_up_sync(0xffffffff, x, off);
            if (t >= off) x += y;
        }
        int c = carry_s;
        if (i < nblocks) g_boff[i] = c + x - v;   // exclusive
        __syncthreads();
        if (t == 31) carry_s = c + x;
        __syncthreads();
    }
}

// Phase 3: finalize offsets + cursors + dis.
__global__ void scan3_kernel(int N) {
    int i = blockIdx.x * blockDim.x + threadIdx.x;
    if (i < N) {
        int incl = g_scan[i] + g_boff[i >> 10];
        int d = g_deg[i];
        g_off[i + 1] = incl;
        g_cur[i]     = incl - d;
        g_dis[i]     = (d > 0) ? rsqrtf((float)d) : 0.0f;
        if (i == 0) g_off[0] = 0;
    }
}

__global__ void scatter_kernel(const int* __restrict__ src,
                               const int* __restrict__ dst, int E, int N) {
    int e = blockIdx.x * blockDim.x + threadIdx.x;
    if (e < E) {
        int d = dst[e];
        int s = src[e];
        if ((unsigned)d < (unsigned)N && (unsigned)s < (unsigned)N) {
            int pos = atomicAdd(&g_cur[d], 1);
            if ((unsigned)pos < (unsigned)MAXE) g_csr[pos] = s;
        }
    }
}

// Initialize acc (=d_out) with emb0 and g_t0 with dis[u]*emb0[u].
__global__ void init_kernel(const float* __restrict__ emb_users,
                            const float* __restrict__ emb_items,
                            float* __restrict__ acc,
                            int nu_elems, int total_elems) {
    int idx = blockIdx.x * blockDim.x + threadIdx.x;
    if (idx < total_elems) {
        float v = (idx < nu_elems) ? emb_users[idx] : emb_items[idx - nu_elems];
        acc[idx] = v;
        g_t0[idx] = g_dis[idx >> 6] * v;
    }
}

// One propagation layer. Warp per node; each lane owns one float2 (2 cols).
__global__ void __launch_bounds__(256)
layer_kernel(float* __restrict__ acc, int N, int inbuf, int last) {
    int gtid = blockIdx.x * blockDim.x + threadIdx.x;
    int node = gtid >> 5;
    int lane = gtid & 31;
    if (node >= N) return;

    const float2* __restrict__ tin =
        (const float2*)(inbuf ? g_t1 : g_t0);
    float2* __restrict__ tout =
        (float2*)(inbuf ? g_t0 : g_t1);

    int s = g_off[node];
    int e = g_off[node + 1];

    float ax = 0.0f, ay = 0.0f;
    int p = s;
    // 4-deep unroll for MLP
    for (; p + 3 < e; p += 4) {
        int u0 = g_csr[p];
        int u1 = g_csr[p + 1];
        int u2 = g_csr[p + 2];
        int u3 = g_csr[p + 3];
        float2 v0 = __ldg(&tin[(size_t)u0 * D2 + lane]);
        float2 v1 = __ldg(&tin[(size_t)u1 * D2 + lane]);
        float2 v2 = __ldg(&tin[(size_t)u2 * D2 + lane]);
        float2 v3 = __ldg(&tin[(size_t)u3 * D2 + lane]);
        ax += v0.x; ay += v0.y;
        ax += v1.x; ay += v1.y;
        ax += v2.x; ay += v2.y;
        ax += v3.x; ay += v3.y;
    }
    for (; p < e; p++) {
        int u0 = g_csr[p];
        float2 v0 = __ldg(&tin[(size_t)u0 * D2 + lane]);
        ax += v0.x; ay += v0.y;
    }

    float dv = g_dis[node];
    float ex = dv * ax;
    float ey = dv * ay;

    size_t oidx = (size_t)node * D2 + lane;
    float2* acc2 = (float2*)acc;
    float2 a = acc2[oidx];
    if (last) {
        const float sc = 1.0f / 25.0f;
        a.x = (a.x + ex) * sc;
        a.y = (a.y + ey) * sc;
        acc2[oidx] = a;
    } else {
        a.x += ex;
        a.y += ey;
        acc2[oidx] = a;
        float2 tv;
        tv.x = dv * ex;
        tv.y = dv * ey;
        tout[oidx] = tv;
    }
}

// -------- launch --------
extern "C" void kernel_launch(void* const* d_in, const int* in_sizes, int n_in,
                              void* d_out, int out_size) {
    const float* emb_users = (const float*)d_in[0];
    const float* emb_items = (const float*)d_in[1];
    const int*   edge      = (const int*)d_in[2];   // int32

    int nu_elems = in_sizes[0];
    int ni_elems = in_sizes[1];
    int E        = in_sizes[2] / 2;
    int NU = nu_elems / D;
    int NI = ni_elems / D;
    int N  = NU + NI;

    const int* src = edge;
    const int* dst = edge + E;
    float* acc = (float*)d_out;

    const int T = 256;
    int nScanBlocks = (N + SCAN_T - 1) / SCAN_T;

    zero_deg_kernel<<<(N + T - 1) / T, T>>>(N);
    count_deg_kernel<<<(E + T - 1) / T, T>>>(dst, E, N);
    scan1_kernel<<<nScanBlocks, SCAN_T>>>(N);
    scan2_kernel<<<1, 32>>>(nScanBlocks);
    scan3_kernel<<<(N + T - 1) / T, T>>>(N);
    scatter_kernel<<<(E + T - 1) / T, T>>>(src, dst, E, N);

    int total = N * D;
    init_kernel<<<(total + T - 1) / T, T>>>(emb_users, emb_items, acc, nu_elems, total);

    int layer_blocks = (N * 32 + T - 1) / T;   // warp per node
    layer_kernel<<<layer_blocks, T>>>(acc, N, 0, 0); // t0 -> t1
    layer_kernel<<<layer_blocks, T>>>(acc, N, 1, 0); // t1 -> t0
    layer_kernel<<<layer_blocks, T>>>(acc, N, 0, 0); // t0 -> t1
    layer_kernel<<<layer_blocks, T>>>(acc, N, 1, 1); // t1, final scale
}

// round 4
// speedup vs baseline: 1.7248x; 1.1349x over previous
#include <cuda_runtime.h>
#include <cuda_fp16.h>
#include <stdint.h>

// Problem shape (fixed by the dataset): 100000 users + 50000 items, D=64, E=2M.
#define MAXN 150016            // padded node count
#define MAXE 2000000
#define D 64
#define D2H 32                 // D in half2
#define SCAN_T 1024
#define MAX_BLOCKS 256         // ceil(MAXN/1024) = 147

// -------- static device scratch (no allocations allowed) --------
__device__ int    g_deg[MAXN];
__device__ float  g_dis[MAXN];
__device__ int    g_off[MAXN + 1];
__device__ int    g_cur[MAXN];
__device__ int    g_csr[MAXE];
__device__ int    g_scan[MAXN];        // inclusive per-block scan
__device__ int    g_bsum[MAX_BLOCKS];  // per-block totals
__device__ int    g_boff[MAX_BLOCKS];  // exclusive scan of block totals
__device__ __half g_t0[(size_t)MAXN * D];
__device__ __half g_t1[(size_t)MAXN * D];

// -------- kernels --------

__global__ void zero_deg_kernel(int N) {
    int i = blockIdx.x * blockDim.x + threadIdx.x;
    if (i < N) g_deg[i] = 0;
}

__global__ void count_deg_kernel(const int* __restrict__ dst, int E, int N) {
    int e = blockIdx.x * blockDim.x + threadIdx.x;
    if (e < E) {
        int d = dst[e];
        if ((unsigned)d < (unsigned)N) atomicAdd(&g_deg[d], 1);
    }
}

// Phase 1: per-block inclusive scan of g_deg (1024 elems/block) via warp shuffles.
__global__ void __launch_bounds__(SCAN_T)
scan1_kernel(int N) {
    __shared__ int wsum[32];
    int t = threadIdx.x;
    int i = blockIdx.x * SCAN_T + t;
    int v = (i < N) ? g_deg[i] : 0;

    int x = v;
    #pragma unroll
    for (int off = 1; off < 32; off <<= 1) {
        int y = __shfl_up_sync(0xffffffff, x, off);
        if ((t & 31) >= off) x += y;
    }
    if ((t & 31) == 31) wsum[t >> 5] = x;
    __syncthreads();

    if (t < 32) {
        int w = wsum[t];
        #pragma unroll
        for (int off = 1; off < 32; off <<= 1) {
            int y = __shfl_up_sync(0xffffffff, w, off);
            if (t >= off) w += y;
        }
        wsum[t] = w;
    }
    __syncthreads();

    int base = (t >= 32) ? wsum[(t >> 5) - 1] : 0;
    int incl = base + x;
    if (i < N) g_scan[i] = incl;
    if (t == SCAN_T - 1) g_bsum[blockIdx.x] = incl;
}

// Phase 2: single warp scans block sums (exclusive) -> g_boff.
__global__ void scan2_kernel(int nblocks) {
    __shared__ int carry_s;
    int t = threadIdx.x;
    if (t == 0) carry_s = 0;
    __syncthreads();
    for (int base = 0; base < nblocks; base += 32) {
        int i = base + t;
        int v = (i < nblocks) ? g_bsum[i] : 0;
        int x = v;
        #pragma unroll
        for (int off = 1; off < 32; off <<= 1) {
            int y = __shfl_up_sync(0xffffffff, x, off);
            if (t >= off) x += y;
        }
        int c = carry_s;
        if (i < nblocks) g_boff[i] = c + x - v;   // exclusive
        __syncthreads();
        if (t == 31) carry_s = c + x;
        __syncthreads();
    }
}

// Phase 3: finalize offsets + cursors + dis.
__global__ void scan3_kernel(int N) {
    int i = blockIdx.x * blockDim.x + threadIdx.x;
    if (i < N) {
        int incl = g_scan[i] + g_boff[i >> 10];
        int d = g_deg[i];
        g_off[i + 1] = incl;
        g_cur[i]     = incl - d;
        g_dis[i]     = (d > 0) ? rsqrtf((float)d) : 0.0f;
        if (i == 0) g_off[0] = 0;
    }
}

__global__ void scatter_kernel(const int* __restrict__ src,
                               const int* __restrict__ dst, int E, int N) {
    int e = blockIdx.x * blockDim.x + threadIdx.x;
    if (e < E) {
        int d = dst[e];
        int s = src[e];
        if ((unsigned)d < (unsigned)N && (unsigned)s < (unsigned)N) {
            int pos = atomicAdd(&g_cur[d], 1);
            if ((unsigned)pos < (unsigned)MAXE) g_csr[pos] = s;
        }
    }
}

// Initialize acc (=d_out) with emb0 and g_t0 with fp16(dis[u]*emb0[u]).
__global__ void init_kernel(const float* __restrict__ emb_users,
                            const float* __restrict__ emb_items,
                            float* __restrict__ acc,
                            int nu_elems, int total_elems) {
    int idx = blockIdx.x * blockDim.x + threadIdx.x;
    if (idx < total_elems) {
        float v = (idx < nu_elems) ? emb_users[idx] : emb_items[idx - nu_elems];
        acc[idx] = v;
        g_t0[idx] = __float2half(g_dis[idx >> 6] * v);
    }
}

// One propagation layer. Warp per node; each lane owns one half2 (2 cols).
// Gather row = 64 halfs = 128B = one L2 line per edge.
__global__ void __launch_bounds__(256)
layer_kernel(float* __restrict__ acc, int N, int inbuf, int last) {
    int gtid = blockIdx.x * blockDim.x + threadIdx.x;
    int node = gtid >> 5;
    int lane = gtid & 31;
    if (node >= N) return;

    const __half2* __restrict__ tin =
        (const __half2*)(inbuf ? g_t1 : g_t0);
    __half2* __restrict__ tout =
        (__half2*)(inbuf ? g_t0 : g_t1);

    int s = g_off[node];
    int e = g_off[node + 1];

    float ax = 0.0f, ay = 0.0f;
    int p = s;
    for (; p + 3 < e; p += 4) {
        int u0 = g_csr[p];
        int u1 = g_csr[p + 1];
        int u2 = g_csr[p + 2];
        int u3 = g_csr[p + 3];
        float2 v0 = __half22float2(__ldg(&tin[(size_t)u0 * D2H + lane]));
        float2 v1 = __half22float2(__ldg(&tin[(size_t)u1 * D2H + lane]));
        float2 v2 = __half22float2(__ldg(&tin[(size_t)u2 * D2H + lane]));
        float2 v3 = __half22float2(__ldg(&tin[(size_t)u3 * D2H + lane]));
        ax += v0.x; ay += v0.y;
        ax += v1.x; ay += v1.y;
        ax += v2.x; ay += v2.y;
        ax += v3.x; ay += v3.y;
    }
    for (; p < e; p++) {
        int u0 = g_csr[p];
        float2 v0 = __half22float2(__ldg(&tin[(size_t)u0 * D2H + lane]));
        ax += v0.x; ay += v0.y;
    }

    float dv = g_dis[node];
    float ex = dv * ax;
    float ey = dv * ay;

    size_t oidx = (size_t)node * 32 + lane;   // float2/half2 index (32 per row)
    float2* acc2 = (float2*)acc;
    float2 a = acc2[oidx];
    if (last) {
        const float sc = 1.0f / 25.0f;
        a.x = (a.x + ex) * sc;
        a.y = (a.y + ey) * sc;
        acc2[oidx] = a;
    } else {
        a.x += ex;
        a.y += ey;
        acc2[oidx] = a;
        tout[oidx] = __floats2half2_rn(dv * ex, dv * ey);
    }
}

// -------- launch --------
extern "C" void kernel_launch(void* const* d_in, const int* in_sizes, int n_in,
                              void* d_out, int out_size) {
    const float* emb_users = (const float*)d_in[0];
    const float* emb_items = (const float*)d_in[1];
    const int*   edge      = (const int*)d_in[2];   // int32

    int nu_elems = in_sizes[0];
    int ni_elems = in_sizes[1];
    int E        = in_sizes[2] / 2;
    int NU = nu_elems / D;
    int NI = ni_elems / D;
    int N  = NU + NI;

    const int* src = edge;
    const int* dst = edge + E;
    float* acc = (float*)d_out;

    const int T = 256;
    int nScanBlocks = (N + SCAN_T - 1) / SCAN_T;

    zero_deg_kernel<<<(N + T - 1) / T, T>>>(N);
    count_deg_kernel<<<(E + T - 1) / T, T>>>(dst, E, N);
    scan1_kernel<<<nScanBlocks, SCAN_T>>>(N);
    scan2_kernel<<<1, 32>>>(nScanBlocks);
    scan3_kernel<<<(N + T - 1) / T, T>>>(N);
    scatter_kernel<<<(E + T - 1) / T, T>>>(src, dst, E, N);

    int total = N * D;
    init_kernel<<<(total + T - 1) / T, T>>>(emb_users, emb_items, acc, nu_elems, total);

    int layer_blocks = (N * 32 + T - 1) / T;   // warp per node
    layer_kernel<<<layer_blocks, T>>>(acc, N, 0, 0); // t0 -> t1
    layer_kernel<<<layer_blocks, T>>>(acc, N, 1, 0); // t1 -> t0
    layer_kernel<<<layer_blocks, T>>>(acc, N, 0, 0); // t0 -> t1
    layer_kernel<<<layer_blocks, T>>>(acc, N, 1, 1); // t1, final scale
}

// round 5
// speedup vs baseline: 2.0663x; 1.1980x over previous
#include <cuda_runtime.h>
#include <cuda_fp16.h>
#include <stdint.h>

// Problem shape: 100000 users + 50000 items, D=64, E=2M.
#define MAXN 150016
#define MAXE 2000000
#define D 64
#define ROW_U2 16              // 64 halfs = 16 uint2 per row
#define SCAN_T 1024
#define MAX_BLOCKS 256
#define NLAYERS 4

// -------- static device scratch --------
__device__ int    g_deg[MAXN];
__device__ float  g_dis[MAXN];
__device__ float  g_inv[MAXN];          // sqrt(deg) (inverse of dis), 0 if deg==0
__device__ int    g_off[MAXN + 1];
__device__ int    g_cur[MAXN];
__device__ int    g_csr[MAXE];
__device__ int    g_scan[MAXN];
__device__ int    g_bsum[MAX_BLOCKS];
__device__ int    g_boff[MAX_BLOCKS];
// t_0..t_4 message buffers, fp16: t_k = dis * e_k
__device__ __half g_t[(size_t)(NLAYERS + 1) * MAXN * D];

// -------- kernels --------

__global__ void zero_deg_kernel(int N) {
    int i = blockIdx.x * blockDim.x + threadIdx.x;
    if (i < N) g_deg[i] = 0;
}

__global__ void count_deg_kernel(const int* __restrict__ dst, int E, int N) {
    int e = blockIdx.x * blockDim.x + threadIdx.x;
    if (e < E) {
        int d = dst[e];
        if ((unsigned)d < (unsigned)N) atomicAdd(&g_deg[d], 1);
    }
}

__global__ void __launch_bounds__(SCAN_T)
scan1_kernel(int N) {
    __shared__ int wsum[32];
    int t = threadIdx.x;
    int i = blockIdx.x * SCAN_T + t;
    int v = (i < N) ? g_deg[i] : 0;

    int x = v;
    #pragma unroll
    for (int off = 1; off < 32; off <<= 1) {
        int y = __shfl_up_sync(0xffffffff, x, off);
        if ((t & 31) >= off) x += y;
    }
    if ((t & 31) == 31) wsum[t >> 5] = x;
    __syncthreads();

    if (t < 32) {
        int w = wsum[t];
        #pragma unroll
        for (int off = 1; off < 32; off <<= 1) {
            int y = __shfl_up_sync(0xffffffff, w, off);
            if (t >= off) w += y;
        }
        wsum[t] = w;
    }
    __syncthreads();

    int base = (t >= 32) ? wsum[(t >> 5) - 1] : 0;
    int incl = base + x;
    if (i < N) g_scan[i] = incl;
    if (t == SCAN_T - 1) g_bsum[blockIdx.x] = incl;
}

__global__ void scan2_kernel(int nblocks) {
    __shared__ int carry_s;
    int t = threadIdx.x;
    if (t == 0) carry_s = 0;
    __syncthreads();
    for (int base = 0; base < nblocks; base += 32) {
        int i = base + t;
        int v = (i < nblocks) ? g_bsum[i] : 0;
        int x = v;
        #pragma unroll
        for (int off = 1; off < 32; off <<= 1) {
            int y = __shfl_up_sync(0xffffffff, x, off);
            if (t >= off) x += y;
        }
        int c = carry_s;
        if (i < nblocks) g_boff[i] = c + x - v;
        __syncthreads();
        if (t == 31) carry_s = c + x;
        __syncthreads();
    }
}

__global__ void scan3_kernel(int N) {
    int i = blockIdx.x * blockDim.x + threadIdx.x;
    if (i < N) {
        int incl = g_scan[i] + g_boff[i >> 10];
        int d = g_deg[i];
        g_off[i + 1] = incl;
        g_cur[i]     = incl - d;
        float fd = (float)d;
        g_dis[i] = (d > 0) ? rsqrtf(fd) : 0.0f;
        g_inv[i] = (d > 0) ? sqrtf(fd)  : 0.0f;
        if (i == 0) g_off[0] = 0;
    }
}

__global__ void scatter_kernel(const int* __restrict__ src,
                               const int* __restrict__ dst, int E, int N) {
    int e = blockIdx.x * blockDim.x + threadIdx.x;
    if (e < E) {
        int d = dst[e];
        int s = src[e];
        if ((unsigned)d < (unsigned)N && (unsigned)s < (unsigned)N) {
            int pos = atomicAdd(&g_cur[d], 1);
            if ((unsigned)pos < (unsigned)MAXE) g_csr[pos] = s;
        }
    }
}

// t0[idx] = fp16(dis[node] * emb0[idx]); no acc write.
__global__ void init_kernel(const float* __restrict__ emb_users,
                            const float* __restrict__ emb_items,
                            int nu_elems, int total_elems) {
    int idx = blockIdx.x * blockDim.x + threadIdx.x;
    if (idx < total_elems) {
        float v = (idx < nu_elems) ? emb_users[idx] : emb_items[idx - nu_elems];
        g_t[idx] = __float2half(g_dis[idx >> 6] * v);
    }
}

// One layer: reads t_{k-1}, writes t_k. Two nodes per warp (16 lanes each),
// each lane gathers 8B (uint2 = 4 halfs). No acc traffic.
__global__ void __launch_bounds__(256)
layer_kernel(int N, int kin) {
    int gtid = blockIdx.x * blockDim.x + threadIdx.x;
    int w    = gtid >> 5;
    int lane = gtid & 31;
    int node = (w << 1) | (lane >> 4);
    int sub  = lane & 15;
    if (node >= N) return;

    const uint2* __restrict__ tin  =
        (const uint2*)(g_t + (size_t)kin * MAXN * D);
    uint2* __restrict__ tout =
        (uint2*)(g_t + (size_t)(kin + 1) * MAXN * D);

    int s = g_off[node];
    int e = g_off[node + 1];

    float ax = 0.f, ay = 0.f, az = 0.f, aw = 0.f;
    int p = s;
    for (; p + 3 < e; p += 4) {
        int u0 = g_csr[p];
        int u1 = g_csr[p + 1];
        int u2 = g_csr[p + 2];
        int u3 = g_csr[p + 3];
        uint2 r0 = __ldg(&tin[(size_t)u0 * ROW_U2 + sub]);
        uint2 r1 = __ldg(&tin[(size_t)u1 * ROW_U2 + sub]);
        uint2 r2 = __ldg(&tin[(size_t)u2 * ROW_U2 + sub]);
        uint2 r3 = __ldg(&tin[(size_t)u3 * ROW_U2 + sub]);
        float2 a0 = __half22float2(*(__half2*)&r0.x);
        float2 b0 = __half22float2(*(__half2*)&r0.y);
        float2 a1 = __half22float2(*(__half2*)&r1.x);
        float2 b1 = __half22float2(*(__half2*)&r1.y);
        float2 a2 = __half22float2(*(__half2*)&r2.x);
        float2 b2 = __half22float2(*(__half2*)&r2.y);
        float2 a3 = __half22float2(*(__half2*)&r3.x);
        float2 b3 = __half22float2(*(__half2*)&r3.y);
        ax += a0.x + a1.x + a2.x + a3.x;
        ay += a0.y + a1.y + a2.y + a3.y;
        az += b0.x + b1.x + b2.x + b3.x;
        aw += b0.y + b1.y + b2.y + b3.y;
    }
    for (; p < e; p++) {
        int u0 = g_csr[p];
        uint2 r0 = __ldg(&tin[(size_t)u0 * ROW_U2 + sub]);
        float2 a0 = __half22float2(*(__half2*)&r0.x);
        float2 b0 = __half22float2(*(__half2*)&r0.y);
        ax += a0.x; ay += a0.y; az += b0.x; aw += b0.y;
    }

    float dv = g_dis[node];
    float d2 = dv * dv;          // t_next = dis * (dis * sum) = dis^2 * sum
    uint2 o;
    __half2 lo = __floats2half2_rn(d2 * ax, d2 * ay);
    __half2 hi = __floats2half2_rn(d2 * az, d2 * aw);
    o.x = *(uint32_t*)&lo;
    o.y = *(uint32_t*)&hi;
    tout[(size_t)node * ROW_U2 + sub] = o;
}

// out = (emb0 + sqrt(deg) * (t1+t2+t3+t4)) / 25, processed as half2/float2 pairs.
__global__ void final_kernel(const float* __restrict__ emb_users,
                             const float* __restrict__ emb_items,
                             float* __restrict__ out,
                             int nu_pairs, int total_pairs) {
    int idx = blockIdx.x * blockDim.x + threadIdx.x;   // half2 index
    if (idx >= total_pairs) return;
    int node = idx >> 5;                               // 32 half2 per row

    const __half2* t1 = (const __half2*)(g_t + (size_t)1 * MAXN * D);
    const __half2* t2 = (const __half2*)(g_t + (size_t)2 * MAXN * D);
    const __half2* t3 = (const __half2*)(g_t + (size_t)3 * MAXN * D);
    const __half2* t4 = (const __half2*)(g_t + (size_t)4 * MAXN * D);

    float2 s1 = __half22float2(t1[idx]);
    float2 s2 = __half22float2(t2[idx]);
    float2 s3 = __half22float2(t3[idx]);
    float2 s4 = __half22float2(t4[idx]);

    const float2* embu = (const float2*)emb_users;
    const float2* embi = (const float2*)emb_items;
    float2 e0 = (idx < nu_pairs) ? embu[idx] : embi[idx - nu_pairs];

    float inv = g_inv[node];
    const float sc = 1.0f / 25.0f;
    float2 r;
    r.x = (e0.x + inv * (s1.x + s2.x + s3.x + s4.x)) * sc;
    r.y = (e0.y + inv * (s1.y + s2.y + s3.y + s4.y)) * sc;
    ((float2*)out)[idx] = r;
}

// -------- launch --------
extern "C" void kernel_launch(void* const* d_in, const int* in_sizes, int n_in,
                              void* d_out, int out_size) {
    const float* emb_users = (const float*)d_in[0];
    const float* emb_items = (const float*)d_in[1];
    const int*   edge      = (const int*)d_in[2];   // int32

    int nu_elems = in_sizes[0];
    int ni_elems = in_sizes[1];
    int E        = in_sizes[2] / 2;
    int NU = nu_elems / D;
    int NI = ni_elems / D;
    int N  = NU + NI;

    const int* src = edge;
    const int* dst = edge + E;
    float* out = (float*)d_out;

    const int T = 256;
    int nScanBlocks = (N + SCAN_T - 1) / SCAN_T;

    zero_deg_kernel<<<(N + T - 1) / T, T>>>(N);
    count_deg_kernel<<<(E + T - 1) / T, T>>>(dst, E, N);
    scan1_kernel<<<nScanBlocks, SCAN_T>>>(N);
    scan2_kernel<<<1, 32>>>(nScanBlocks);
    scan3_kernel<<<(N + T - 1) / T, T>>>(N);
    scatter_kernel<<<(E + T - 1) / T, T>>>(src, dst, E, N);

    int total = N * D;
    init_kernel<<<(total + T - 1) / T, T>>>(emb_users, emb_items, nu_elems, total);

    // 2 nodes per warp -> N/2 warps -> N*16 threads
    int layer_blocks = (N * 16 + T - 1) / T;
    layer_kernel<<<layer_blocks, T>>>(N, 0);
    layer_kernel<<<layer_blocks, T>>>(N, 1);
    layer_kernel<<<layer_blocks, T>>>(N, 2);
    layer_kernel<<<layer_blocks, T>>>(N, 3);

    int total_pairs = N * (D / 2);
    final_kernel<<<(total_pairs + T - 1) / T, T>>>(emb_users, emb_items, out,
                                                   nu_elems / 2, total_pairs);
}